// round 10
// baseline (speedup 1.0000x reference)
#include <cuda_runtime.h>
#include <math.h>
#include <stdint.h>

// Shapes: B=4, S=2048, H=2048, I=5504, E=8, R=16, top-2
#define M_ROWS  8192
#define I_DIM   5504
#define H_DIM   2048

#define BM 256
#define BN 128
#define BK 32
#define NSTAGE 4
#define ABYTES (BM * 128)            // 32768
#define BBYTES (BN * 128)            // 16384
#define PAIRBYTES (ABYTES + BBYTES)  // 49152
#define AWORDS (ABYTES / 4)          // 8192
#define PAIRWORDS (PAIRBYTES / 4)    // 12288
#define DSMEM (NSTAGE * PAIRBYTES)   // 196608

// ---------------- scratch ----------------
__device__ float g_gate[45088768];   // 8192*5504 (holds h after gate GEMM)
__device__ float g_up  [45088768];
__device__ float g_xc  [16777216];   // tf32-rounded x
__device__ float g_wgc [11272192];   // tf32-rounded Wg
__device__ float g_wuc [11272192];
__device__ float g_wdc [11272192];
__device__ float g_u   [8192*64];
__device__ float g_v   [8192*32];
__device__ int   g_sel [8];

// ---------------- helpers ----------------
__device__ __forceinline__ uint32_t smem_u32(const void* p) {
    uint32_t a;
    asm("{ .reg .u64 t; cvta.to.shared.u64 t, %1; cvt.u32.u64 %0, t; }" : "=r"(a) : "l"(p));
    return a;
}
__device__ __forceinline__ uint32_t f2tf(float x) {
    uint32_t r; asm("cvt.rna.tf32.f32 %0, %1;" : "=r"(r) : "f"(x)); return r;
}
__device__ __forceinline__ void sts128(uint32_t a, uint32_t x, uint32_t y, uint32_t z, uint32_t w) {
    asm volatile("st.shared.v4.b32 [%0], {%1,%2,%3,%4};" :: "r"(a), "r"(x), "r"(y), "r"(z), "r"(w) : "memory");
}
__device__ __forceinline__ void cpasync16(uint32_t dst, const void* src) {
    asm volatile("cp.async.cg.shared.global [%0], [%1], 16;" :: "r"(dst), "l"(src) : "memory");
}
__device__ __forceinline__ void cp_commit() {
    asm volatile("cp.async.commit_group;" ::: "memory");
}
template<int N>
__device__ __forceinline__ void cp_wait() {
    asm volatile("cp.async.wait_group %0;" :: "n"(N) : "memory");
}
__device__ __forceinline__ void mma_tf32(float* c,
                                         uint32_t a0, uint32_t a1, uint32_t a2, uint32_t a3,
                                         uint32_t b0, uint32_t b1) {
    asm volatile(
        "mma.sync.aligned.m16n8k8.row.col.f32.tf32.tf32.f32 "
        "{%0,%1,%2,%3},{%4,%5,%6,%7},{%8,%9},{%0,%1,%2,%3};"
        : "+f"(c[0]), "+f"(c[1]), "+f"(c[2]), "+f"(c[3])
        : "r"(a0), "r"(a1), "r"(a2), "r"(a3), "r"(b0), "r"(b1));
}
__device__ __forceinline__ float silu(float x) {
    return x / (1.f + expf(-x));
}

// ---------------- tf32 rounding pass ----------------
__global__ void cvt_tf32_kernel(const float* __restrict__ in, float* __restrict__ out, int n4)
{
    int i = blockIdx.x * blockDim.x + threadIdx.x;
    if (i >= n4) return;
    float4 v = reinterpret_cast<const float4*>(in)[i];
    uint4 o = make_uint4(f2tf(v.x), f2tf(v.y), f2tf(v.z), f2tf(v.w));
    reinterpret_cast<uint4*>(out)[i] = o;
}

// ---------------- top-2 gating ----------------
__global__ void topk_kernel(const float* __restrict__ gv) {
    int b = threadIdx.x;
    if (b >= 4) return;
    const float* r = gv + b * 8;
    int i0 = 0; float v0 = r[0];
    #pragma unroll
    for (int e = 1; e < 8; e++) if (r[e] > v0) { v0 = r[e]; i0 = e; }
    int i1 = -1; float v1 = -3.4e38f;
    #pragma unroll
    for (int e = 0; e < 8; e++) if (e != i0 && r[e] > v1) { v1 = r[e]; i1 = e; }
    g_sel[2*b] = i0; g_sel[2*b+1] = i1;
}

// ---------------- U = X @ A_sel (32 cols: 2 experts x r=16) ----------------
__global__ void lora_proj_kernel(const float* __restrict__ X,
                                 const float* __restrict__ A,
                                 int K, float* __restrict__ U,
                                 int ustride, int uoff)
{
    __shared__ float Xs[8][128];
    int tid = threadIdx.x;
    int col = tid & 31, lr = tid >> 5;
    int row0 = blockIdx.x * 8;
    int b = row0 >> 11;
    int e = g_sel[2*b + (col >> 4)];
    int r = col & 15;
    const float* Ap = A + (size_t)e * K * 16 + r;

    float acc = 0.f;
    for (int k0 = 0; k0 < K; k0 += 128) {
        int flat = tid * 4;
        int rr = flat >> 7, cc = flat & 127;
        *reinterpret_cast<float4*>(&Xs[rr][cc]) =
            *reinterpret_cast<const float4*>(X + (size_t)(row0 + rr) * K + k0 + cc);
        __syncthreads();
        #pragma unroll 8
        for (int kk = 0; kk < 128; kk++)
            acc += Xs[lr][kk] * Ap[(size_t)(k0 + kk) * 16];
        __syncthreads();
    }
    U[(size_t)(row0 + lr) * ustride + uoff + col] = acc;
}

// ---------------- tf32 mma.sync GEMM, cp.async 4-stage, 256x128 tile ----------------
// A, W pre-rounded to tf32. C = A @ W^T + U @ (2*Bl_sel)
// If Up != nullptr: epilogue writes f2tf(silu(acc) * Up[m,n]) instead of acc.
__global__ void __launch_bounds__(256, 1)
gemm_mma_kernel(const float* __restrict__ A, const float* __restrict__ W,
                const float* __restrict__ U, int ustride, int uoff,
                const float* __restrict__ Bl,
                const float* __restrict__ Up,
                float* __restrict__ C, int N, int K)
{
    extern __shared__ __align__(128) uint32_t smem_u[];
    uint32_t smem_base = smem_u32(smem_u);

    int tid  = threadIdx.x;
    int wid  = tid >> 5, lane = tid & 31;
    int g    = lane >> 2, tig = lane & 3;
    int warp_m = (wid >> 1) * 64;
    int warp_n = (wid & 1) * 64;
    int row0 = blockIdx.y * BM, col0 = blockIdx.x * BN;
    int bb   = row0 >> 11;
    int e0 = g_sel[2*bb], e1 = g_sel[2*bb+1];

    float acc[4][8][4];
    #pragma unroll
    for (int i = 0; i < 4; i++)
        #pragma unroll
        for (int j = 0; j < 8; j++)
            #pragma unroll
            for (int q = 0; q < 4; q++) acc[i][j][q] = 0.f;

    // loader geometry: 8 threads/row, 16B each
    int lr  = tid >> 3;                 // 0..31
    int seg = tid & 7;
    int c4  = seg << 2;
    uint32_t dstA[8], dstB[4];
    #pragma unroll
    for (int j = 0; j < 8; j++)
        dstA[j] = (uint32_t)((lr + 32*j) * 128 + 16 * (seg ^ (lr & 7)));
    #pragma unroll
    for (int j = 0; j < 4; j++)
        dstB[j] = (uint32_t)((lr + 32*j) * 128 + 16 * (seg ^ (lr & 7)));

    const float* aptr = A + (size_t)(row0 + lr) * K + c4;
    const float* wptr = W + (size_t)(col0 + lr) * K + c4;

    int nk = K >> 5;
    int ntot = nk + 1;

    auto issue_chunk = [&](int i) {
        int buf = i & (NSTAGE - 1);
        uint32_t a_s = smem_base + (uint32_t)buf * PAIRBYTES;
        uint32_t b_s = a_s + ABYTES;
        if (i < nk) {
            const float* ap = aptr + (i << 5);
            const float* wp = wptr + (i << 5);
            #pragma unroll
            for (int j = 0; j < 8; j++)
                cpasync16(a_s + dstA[j], ap + (size_t)(32 * j) * K);
            #pragma unroll
            for (int j = 0; j < 4; j++)
                cpasync16(b_s + dstB[j], wp + (size_t)(32 * j) * K);
        } else {
            // LoRA chunk: A-part = U[row, 0:32], B-part[n][k] = 2*Bl[e(k), k&15, col0+n]
            #pragma unroll
            for (int j = 0; j < 8; j++) {
                float4 uv = *reinterpret_cast<const float4*>(
                    U + (size_t)(row0 + lr + 32*j) * ustride + uoff + c4);
                sts128(a_s + dstA[j], f2tf(uv.x), f2tf(uv.y), f2tf(uv.z), f2tf(uv.w));
            }
            int e = (seg < 4) ? e0 : e1;
            #pragma unroll
            for (int j = 0; j < 4; j++) {
                int n = lr + 32*j;
                float f[4];
                #pragma unroll
                for (int t = 0; t < 4; t++) {
                    int k = c4 + t;
                    f[t] = 2.0f * Bl[((size_t)(e * 16 + (k & 15))) * N + col0 + n];
                }
                sts128(b_s + dstB[j], f2tf(f[0]), f2tf(f[1]), f2tf(f[2]), f2tf(f[3]));
            }
        }
        cp_commit();
    };

    // prologue: stages 0,1,2
    issue_chunk(0);
    issue_chunk(1);
    issue_chunk(2);

    int xr = 4 * g;   // fragment xor term

    // fragment double buffers
    uint32_t fa[2][16], fb[2][16];

    for (int i = 0; i < ntot; i++) {
        cp_wait<2>();
        __syncthreads();

        if (i + 3 < ntot) issue_chunk(i + 3);
        else cp_commit();   // keep group accounting uniform

        int buf = i & (NSTAGE - 1);
        const uint32_t* As_ = smem_u + buf * PAIRWORDS;
        const uint32_t* Ws_ = As_ + AWORDS;

        // load fragments for ks=0
        {
            int c_lo = tig ^ xr;
            int c_hi = (tig + 4) ^ xr;
            #pragma unroll
            for (int nt = 0; nt < 8; nt++) {
                int n = warp_n + nt * 8 + g;
                fb[0][nt]     = Ws_[n * 32 + c_lo];
                fb[0][8 + nt] = Ws_[n * 32 + c_hi];
            }
            #pragma unroll
            for (int mt = 0; mt < 4; mt++) {
                int m = warp_m + mt * 16 + g;
                fa[0][mt*4+0] = As_[m * 32 + c_lo];
                fa[0][mt*4+1] = As_[(m + 8) * 32 + c_lo];
                fa[0][mt*4+2] = As_[m * 32 + c_hi];
                fa[0][mt*4+3] = As_[(m + 8) * 32 + c_hi];
            }
        }

        #pragma unroll
        for (int ks = 0; ks < 4; ks++) {
            int pb = ks & 1;
            if (ks < 3) {
                int kk = (ks + 1) << 3;
                int c_lo = (kk + tig) ^ xr;
                int c_hi = (kk + tig + 4) ^ xr;
                int pn = pb ^ 1;
                #pragma unroll
                for (int nt = 0; nt < 8; nt++) {
                    int n = warp_n + nt * 8 + g;
                    fb[pn][nt]     = Ws_[n * 32 + c_lo];
                    fb[pn][8 + nt] = Ws_[n * 32 + c_hi];
                }
                #pragma unroll
                for (int mt = 0; mt < 4; mt++) {
                    int m = warp_m + mt * 16 + g;
                    fa[pn][mt*4+0] = As_[m * 32 + c_lo];
                    fa[pn][mt*4+1] = As_[(m + 8) * 32 + c_lo];
                    fa[pn][mt*4+2] = As_[m * 32 + c_hi];
                    fa[pn][mt*4+3] = As_[(m + 8) * 32 + c_hi];
                }
            }
            #pragma unroll
            for (int mt = 0; mt < 4; mt++) {
                #pragma unroll
                for (int nt = 0; nt < 8; nt++)
                    mma_tf32(acc[mt][nt],
                             fa[pb][mt*4+0], fa[pb][mt*4+1], fa[pb][mt*4+2], fa[pb][mt*4+3],
                             fb[pb][nt], fb[pb][8 + nt]);
            }
        }
    }

    // ---- epilogue ----
    if (Up == nullptr) {
        #pragma unroll
        for (int mt = 0; mt < 4; mt++) {
            int m = row0 + warp_m + mt * 16 + g;
            #pragma unroll
            for (int nt = 0; nt < 8; nt++) {
                int n = col0 + warp_n + nt * 8 + tig * 2;
                float2* p0 = reinterpret_cast<float2*>(C + (size_t)m * N + n);
                float2* p1 = reinterpret_cast<float2*>(C + (size_t)(m + 8) * N + n);
                *p0 = make_float2(acc[mt][nt][0], acc[mt][nt][1]);
                *p1 = make_float2(acc[mt][nt][2], acc[mt][nt][3]);
            }
        }
    } else {
        // fused SwiGLU: h = tf32round(silu(gate) * up)
        #pragma unroll
        for (int mt = 0; mt < 4; mt++) {
            int m = row0 + warp_m + mt * 16 + g;
            #pragma unroll
            for (int nt = 0; nt < 8; nt++) {
                int n = col0 + warp_n + nt * 8 + tig * 2;
                const float2* u0 = reinterpret_cast<const float2*>(Up + (size_t)m * N + n);
                const float2* u1 = reinterpret_cast<const float2*>(Up + (size_t)(m + 8) * N + n);
                float2 up0 = *u0, up1 = *u1;
                uint2* p0 = reinterpret_cast<uint2*>(C + (size_t)m * N + n);
                uint2* p1 = reinterpret_cast<uint2*>(C + (size_t)(m + 8) * N + n);
                *p0 = make_uint2(f2tf(silu(acc[mt][nt][0]) * up0.x),
                                 f2tf(silu(acc[mt][nt][1]) * up0.y));
                *p1 = make_uint2(f2tf(silu(acc[mt][nt][2]) * up1.x),
                                 f2tf(silu(acc[mt][nt][3]) * up1.y));
            }
        }
    }
}

// ---------------- launch ----------------
extern "C" void kernel_launch(void* const* d_in, const int* in_sizes, int n_in,
                              void* d_out, int out_size)
{
    const float* x  = (const float*)d_in[0];
    const float* gv = (const float*)d_in[1];
    const float* Wg = (const float*)d_in[2];
    const float* Ag = (const float*)d_in[3];
    const float* Bg = (const float*)d_in[4];
    const float* Wu = (const float*)d_in[5];
    const float* Au = (const float*)d_in[6];
    const float* Bu = (const float*)d_in[7];
    const float* Wd = (const float*)d_in[8];
    const float* Ad = (const float*)d_in[9];
    const float* Bd = (const float*)d_in[10];
    float* out = (float*)d_out;

    float *gate, *up, *u, *v, *xc, *wgc, *wuc, *wdc;
    cudaGetSymbolAddress((void**)&gate, g_gate);
    cudaGetSymbolAddress((void**)&up,   g_up);
    cudaGetSymbolAddress((void**)&u,    g_u);
    cudaGetSymbolAddress((void**)&v,    g_v);
    cudaGetSymbolAddress((void**)&xc,   g_xc);
    cudaGetSymbolAddress((void**)&wgc,  g_wgc);
    cudaGetSymbolAddress((void**)&wuc,  g_wuc);
    cudaGetSymbolAddress((void**)&wdc,  g_wdc);

    cudaFuncSetAttribute(gemm_mma_kernel, cudaFuncAttributeMaxDynamicSharedMemorySize, DSMEM);

    topk_kernel<<<1, 4>>>(gv);

    // pre-round operands to tf32
    cvt_tf32_kernel<<<(16777216/4 + 255)/256, 256>>>(x,  xc,  16777216/4);
    cvt_tf32_kernel<<<(11272192/4 + 255)/256, 256>>>(Wg, wgc, 11272192/4);
    cvt_tf32_kernel<<<(11272192/4 + 255)/256, 256>>>(Wu, wuc, 11272192/4);
    cvt_tf32_kernel<<<(11272192/4 + 255)/256, 256>>>(Wd, wdc, 11272192/4);

    lora_proj_kernel<<<1024, 256>>>(x, Ag, H_DIM, u, 64, 0);
    lora_proj_kernel<<<1024, 256>>>(x, Au, H_DIM, u, 64, 32);

    // up GEMM first, then gate GEMM with fused SwiGLU epilogue -> h (in g_gate)
    gemm_mma_kernel<<<dim3(I_DIM/BN, M_ROWS/BM), 256, DSMEM>>>(xc, wuc, u, 64, 32, Bu, nullptr, up,   I_DIM, H_DIM);
    gemm_mma_kernel<<<dim3(I_DIM/BN, M_ROWS/BM), 256, DSMEM>>>(xc, wgc, u, 64, 0,  Bg, up,      gate, I_DIM, H_DIM);

    lora_proj_kernel<<<1024, 256>>>(gate, Ad, I_DIM, v, 32, 0);

    gemm_mma_kernel<<<dim3(H_DIM/BN, M_ROWS/BM), 256, DSMEM>>>(gate, wdc, v, 32, 0, Bd, nullptr, out, H_DIM, I_DIM);
}

// round 14
// speedup vs baseline: 1.3799x; 1.3799x over previous
#include <cuda_runtime.h>
#include <cuda_fp16.h>
#include <math.h>
#include <stdint.h>

// Shapes: B=4, S=2048, H=2048, I=5504, E=8, R=16, top-2
#define M_ROWS  8192
#define I_DIM   5504
#define H_DIM   2048

#define BM 256
#define BN 128
#define BK 64                         // fp16: 64 elems = 128 bytes per row
#define NSTAGE 4
#define ABYTES (BM * 128)             // 32768
#define BBYTES (BN * 128)             // 16384
#define PAIRBYTES (ABYTES + BBYTES)   // 49152
#define AWORDS (ABYTES / 4)
#define PAIRWORDS (PAIRBYTES / 4)
#define DSMEM (NSTAGE * PAIRBYTES)    // 196608

// ---------------- scratch ----------------
__device__ __half g_h  [45088768];   // h = silu(gate)*up, fp16
__device__ float  g_up [45088768];   // up GEMM result, fp32
__device__ __half g_xh [16777216];   // fp16 x
__device__ __half g_wgh[11272192];
__device__ __half g_wuh[11272192];
__device__ __half g_wdh[11272192];
__device__ float  g_u  [8192*64];
__device__ float  g_v  [8192*32];
__device__ int    g_sel[8];

// ---------------- helpers ----------------
__device__ __forceinline__ uint32_t smem_u32(const void* p) {
    uint32_t a;
    asm("{ .reg .u64 t; cvta.to.shared.u64 t, %1; cvt.u32.u64 %0, t; }" : "=r"(a) : "l"(p));
    return a;
}
__device__ __forceinline__ uint32_t h2u(__half2 h) {
    return *reinterpret_cast<uint32_t*>(&h);
}
__device__ __forceinline__ void sts128(uint32_t a, uint32_t x, uint32_t y, uint32_t z, uint32_t w) {
    asm volatile("st.shared.v4.b32 [%0], {%1,%2,%3,%4};" :: "r"(a), "r"(x), "r"(y), "r"(z), "r"(w) : "memory");
}
__device__ __forceinline__ void cpasync16(uint32_t dst, const void* src) {
    asm volatile("cp.async.cg.shared.global [%0], [%1], 16;" :: "r"(dst), "l"(src) : "memory");
}
__device__ __forceinline__ void cp_commit() {
    asm volatile("cp.async.commit_group;" ::: "memory");
}
template<int N>
__device__ __forceinline__ void cp_wait() {
    asm volatile("cp.async.wait_group %0;" :: "n"(N) : "memory");
}
__device__ __forceinline__ void mma_fp16(float* c,
                                         uint32_t a0, uint32_t a1, uint32_t a2, uint32_t a3,
                                         uint32_t b0, uint32_t b1) {
    asm volatile(
        "mma.sync.aligned.m16n8k16.row.col.f32.f16.f16.f32 "
        "{%0,%1,%2,%3},{%4,%5,%6,%7},{%8,%9},{%0,%1,%2,%3};"
        : "+f"(c[0]), "+f"(c[1]), "+f"(c[2]), "+f"(c[3])
        : "r"(a0), "r"(a1), "r"(a2), "r"(a3), "r"(b0), "r"(b1));
}
__device__ __forceinline__ float silu(float x) {
    return x / (1.f + expf(-x));
}

// ---------------- fp32 -> fp16 pass (8 elems/thread) ----------------
__global__ void cvt_f2h_kernel(const float* __restrict__ in, __half* __restrict__ out, int n8)
{
    int i = blockIdx.x * blockDim.x + threadIdx.x;
    if (i >= n8) return;
    float4 v0 = reinterpret_cast<const float4*>(in)[2*i];
    float4 v1 = reinterpret_cast<const float4*>(in)[2*i+1];
    uint4 o;
    o.x = h2u(__floats2half2_rn(v0.x, v0.y));
    o.y = h2u(__floats2half2_rn(v0.z, v0.w));
    o.z = h2u(__floats2half2_rn(v1.x, v1.y));
    o.w = h2u(__floats2half2_rn(v1.z, v1.w));
    reinterpret_cast<uint4*>(out)[i] = o;
}

// ---------------- top-2 gating ----------------
__global__ void topk_kernel(const float* __restrict__ gv) {
    int b = threadIdx.x;
    if (b >= 4) return;
    const float* r = gv + b * 8;
    int i0 = 0; float v0 = r[0];
    #pragma unroll
    for (int e = 1; e < 8; e++) if (r[e] > v0) { v0 = r[e]; i0 = e; }
    int i1 = -1; float v1 = -3.4e38f;
    #pragma unroll
    for (int e = 0; e < 8; e++) if (e != i0 && r[e] > v1) { v1 = r[e]; i1 = e; }
    g_sel[2*b] = i0; g_sel[2*b+1] = i1;
}

// ---------------- U = X @ A_sel (32 cols: 2 experts x r=16) ----------------
template<typename T>
__global__ void lora_proj_kernel(const T* __restrict__ X,
                                 const float* __restrict__ A,
                                 int K, float* __restrict__ U,
                                 int ustride, int uoff)
{
    __shared__ float Xs[8][128];
    int tid = threadIdx.x;
    int col = tid & 31, lr = tid >> 5;
    int row0 = blockIdx.x * 8;
    int b = row0 >> 11;
    int e = g_sel[2*b + (col >> 4)];
    int r = col & 15;
    const float* Ap = A + (size_t)e * K * 16 + r;

    float acc = 0.f;
    for (int k0 = 0; k0 < K; k0 += 128) {
        int flat = tid * 4;
        int rr = flat >> 7, cc = flat & 127;
        #pragma unroll
        for (int t = 0; t < 4; t++)
            Xs[rr][cc + t] = (float)X[(size_t)(row0 + rr) * K + k0 + cc + t];
        __syncthreads();
        #pragma unroll 8
        for (int kk = 0; kk < 128; kk++)
            acc += Xs[lr][kk] * Ap[(size_t)(k0 + kk) * 16];
        __syncthreads();
    }
    U[(size_t)(row0 + lr) * ustride + uoff + col] = acc;
}

// ---------------- fp16 mma.sync GEMM, cp.async 4-stage, 256x128 tile ----------------
// C = A @ W^T + U @ (2*Bl_sel). A,W fp16 (pre-rounded). LoRA: zero-padded K-chunk.
// Up == nullptr -> write fp32 C; else write Ch = half(silu(acc)*Up).
__global__ void __launch_bounds__(256, 1)
gemm_mma_kernel(const __half* __restrict__ A, const __half* __restrict__ W,
                const float* __restrict__ U, int ustride, int uoff,
                const float* __restrict__ Bl,
                const float* __restrict__ Up,
                float* __restrict__ C, __half* __restrict__ Ch,
                int N, int K)
{
    extern __shared__ __align__(128) uint32_t smem_u[];
    uint32_t smem_base = smem_u32(smem_u);

    int tid  = threadIdx.x;
    int wid  = tid >> 5, lane = tid & 31;
    int g    = lane >> 2, tig = lane & 3;
    int warp_m = (wid >> 1) * 64;
    int warp_n = (wid & 1) * 64;
    int row0 = blockIdx.y * BM, col0 = blockIdx.x * BN;
    int bb   = row0 >> 11;
    int e0 = g_sel[2*bb], e1 = g_sel[2*bb+1];

    float acc[4][8][4];
    #pragma unroll
    for (int i = 0; i < 4; i++)
        #pragma unroll
        for (int j = 0; j < 8; j++)
            #pragma unroll
            for (int q = 0; q < 4; q++) acc[i][j][q] = 0.f;

    // loader: 8 threads/row, 16B (8 fp16) each
    int lr  = tid >> 3;                 // 0..31
    int seg = tid & 7;                  // 0..7
    uint32_t dstA[8], dstB[4];
    #pragma unroll
    for (int j = 0; j < 8; j++)
        dstA[j] = (uint32_t)((lr + 32*j) * 128 + 16 * (seg ^ (lr & 7)));
    #pragma unroll
    for (int j = 0; j < 4; j++)
        dstB[j] = (uint32_t)((lr + 32*j) * 128 + 16 * (seg ^ (lr & 7)));

    const __half* aptr = A + (size_t)(row0 + lr) * K + seg * 8;
    const __half* wptr = W + (size_t)(col0 + lr) * K + seg * 8;

    int nk = K >> 6;                    // 64-wide chunks
    int ntot = nk + 1;

    auto issue_chunk = [&](int i) {
        int buf = i & (NSTAGE - 1);
        uint32_t a_s = smem_base + (uint32_t)buf * PAIRBYTES;
        uint32_t b_s = a_s + ABYTES;
        if (i < nk) {
            const __half* ap = aptr + (i << 6);
            const __half* wp = wptr + (i << 6);
            #pragma unroll
            for (int j = 0; j < 8; j++)
                cpasync16(a_s + dstA[j], ap + (size_t)(32 * j) * K);
            #pragma unroll
            for (int j = 0; j < 4; j++)
                cpasync16(b_s + dstB[j], wp + (size_t)(32 * j) * K);
        } else {
            // LoRA chunk (rank 32, zero-padded to 64):
            // A-part[m][k] = U[row0+m][uoff+k] (k<32), B-part[n][k] = 2*Bl[e(k),k&15,col0+n] (k<32)
            if (seg < 4) {
                int cbase = seg * 8;
                #pragma unroll
                for (int j = 0; j < 8; j++) {
                    const float* us = U + (size_t)(row0 + lr + 32*j) * ustride + uoff + cbase;
                    float4 u0 = *reinterpret_cast<const float4*>(us);
                    float4 u1 = *reinterpret_cast<const float4*>(us + 4);
                    sts128(a_s + dstA[j],
                           h2u(__floats2half2_rn(u0.x, u0.y)), h2u(__floats2half2_rn(u0.z, u0.w)),
                           h2u(__floats2half2_rn(u1.x, u1.y)), h2u(__floats2half2_rn(u1.z, u1.w)));
                }
                int e = (seg < 2) ? e0 : e1;
                #pragma unroll
                for (int j = 0; j < 4; j++) {
                    int n = lr + 32*j;
                    float f[8];
                    #pragma unroll
                    for (int t = 0; t < 8; t++) {
                        int k = cbase + t;
                        f[t] = 2.0f * Bl[((size_t)(e * 16 + (k & 15))) * N + col0 + n];
                    }
                    sts128(b_s + dstB[j],
                           h2u(__floats2half2_rn(f[0], f[1])), h2u(__floats2half2_rn(f[2], f[3])),
                           h2u(__floats2half2_rn(f[4], f[5])), h2u(__floats2half2_rn(f[6], f[7])));
                }
            } else {
                #pragma unroll
                for (int j = 0; j < 8; j++) sts128(a_s + dstA[j], 0u, 0u, 0u, 0u);
                #pragma unroll
                for (int j = 0; j < 4; j++) sts128(b_s + dstB[j], 0u, 0u, 0u, 0u);
            }
        }
        cp_commit();
    };

    // prologue
    issue_chunk(0);
    issue_chunk(1);
    issue_chunk(2);

    // swizzled word fetch: word w (half2 index 0..31) of row m
    auto ldw = [&](const uint32_t* P, int m, int w) {
        return P[(m << 5) + (((w >> 2) ^ (m & 7)) << 2) + (w & 3)];
    };

    for (int i = 0; i < ntot; i++) {
        cp_wait<2>();
        __syncthreads();

        if (i + 3 < ntot) issue_chunk(i + 3);
        else cp_commit();

        int buf = i & (NSTAGE - 1);
        const uint32_t* As_ = smem_u + buf * PAIRWORDS;
        const uint32_t* Ws_ = As_ + AWORDS;

        #pragma unroll
        for (int ks = 0; ks < 4; ks++) {       // 4 x k16 per 64-chunk
            int w_lo = (ks << 3) + tig;
            int w_hi = w_lo + 4;
            uint32_t b0[8], b1[8];
            #pragma unroll
            for (int nt = 0; nt < 8; nt++) {
                int n = warp_n + nt * 8 + g;
                b0[nt] = ldw(Ws_, n, w_lo);
                b1[nt] = ldw(Ws_, n, w_hi);
            }
            #pragma unroll
            for (int mt = 0; mt < 4; mt++) {
                int m = warp_m + mt * 16 + g;
                uint32_t a0 = ldw(As_, m, w_lo);
                uint32_t a1 = ldw(As_, m + 8, w_lo);
                uint32_t a2 = ldw(As_, m, w_hi);
                uint32_t a3 = ldw(As_, m + 8, w_hi);
                #pragma unroll
                for (int nt = 0; nt < 8; nt++)
                    mma_fp16(acc[mt][nt], a0, a1, a2, a3, b0[nt], b1[nt]);
            }
        }
    }

    // ---- epilogue ----
    if (Up == nullptr) {
        #pragma unroll
        for (int mt = 0; mt < 4; mt++) {
            int m = row0 + warp_m + mt * 16 + g;
            #pragma unroll
            for (int nt = 0; nt < 8; nt++) {
                int n = col0 + warp_n + nt * 8 + tig * 2;
                float2* p0 = reinterpret_cast<float2*>(C + (size_t)m * N + n);
                float2* p1 = reinterpret_cast<float2*>(C + (size_t)(m + 8) * N + n);
                *p0 = make_float2(acc[mt][nt][0], acc[mt][nt][1]);
                *p1 = make_float2(acc[mt][nt][2], acc[mt][nt][3]);
            }
        }
    } else {
        // fused SwiGLU: h = fp16(silu(gate) * up)
        #pragma unroll
        for (int mt = 0; mt < 4; mt++) {
            int m = row0 + warp_m + mt * 16 + g;
            #pragma unroll
            for (int nt = 0; nt < 8; nt++) {
                int n = col0 + warp_n + nt * 8 + tig * 2;
                float2 up0 = *reinterpret_cast<const float2*>(Up + (size_t)m * N + n);
                float2 up1 = *reinterpret_cast<const float2*>(Up + (size_t)(m + 8) * N + n);
                uint32_t* p0 = reinterpret_cast<uint32_t*>(Ch + (size_t)m * N + n);
                uint32_t* p1 = reinterpret_cast<uint32_t*>(Ch + (size_t)(m + 8) * N + n);
                *p0 = h2u(__floats2half2_rn(silu(acc[mt][nt][0]) * up0.x,
                                            silu(acc[mt][nt][1]) * up0.y));
                *p1 = h2u(__floats2half2_rn(silu(acc[mt][nt][2]) * up1.x,
                                            silu(acc[mt][nt][3]) * up1.y));
            }
        }
    }
}

// ---------------- launch ----------------
extern "C" void kernel_launch(void* const* d_in, const int* in_sizes, int n_in,
                              void* d_out, int out_size)
{
    const float* x  = (const float*)d_in[0];
    const float* gv = (const float*)d_in[1];
    const float* Wg = (const float*)d_in[2];
    const float* Ag = (const float*)d_in[3];
    const float* Bg = (const float*)d_in[4];
    const float* Wu = (const float*)d_in[5];
    const float* Au = (const float*)d_in[6];
    const float* Bu = (const float*)d_in[7];
    const float* Wd = (const float*)d_in[8];
    const float* Ad = (const float*)d_in[9];
    const float* Bd = (const float*)d_in[10];
    float* out = (float*)d_out;

    float *up, *u, *v;
    __half *hbuf, *xh, *wgh, *wuh, *wdh;
    cudaGetSymbolAddress((void**)&hbuf, g_h);
    cudaGetSymbolAddress((void**)&up,   g_up);
    cudaGetSymbolAddress((void**)&u,    g_u);
    cudaGetSymbolAddress((void**)&v,    g_v);
    cudaGetSymbolAddress((void**)&xh,   g_xh);
    cudaGetSymbolAddress((void**)&wgh,  g_wgh);
    cudaGetSymbolAddress((void**)&wuh,  g_wuh);
    cudaGetSymbolAddress((void**)&wdh,  g_wdh);

    cudaFuncSetAttribute(gemm_mma_kernel, cudaFuncAttributeMaxDynamicSharedMemorySize, DSMEM);

    topk_kernel<<<1, 4>>>(gv);

    // fp32 -> fp16 operand conversion
    cvt_f2h_kernel<<<(16777216/8 + 255)/256, 256>>>(x,  xh,  16777216/8);
    cvt_f2h_kernel<<<(11272192/8 + 255)/256, 256>>>(Wg, wgh, 11272192/8);
    cvt_f2h_kernel<<<(11272192/8 + 255)/256, 256>>>(Wu, wuh, 11272192/8);
    cvt_f2h_kernel<<<(11272192/8 + 255)/256, 256>>>(Wd, wdh, 11272192/8);

    lora_proj_kernel<float><<<1024, 256>>>(x, Ag, H_DIM, u, 64, 0);
    lora_proj_kernel<float><<<1024, 256>>>(x, Au, H_DIM, u, 64, 32);

    // up GEMM (fp32 out), then gate GEMM with fused SwiGLU -> h (fp16)
    gemm_mma_kernel<<<dim3(I_DIM/BN, M_ROWS/BM), 256, DSMEM>>>(
        xh, wuh, u, 64, 32, Bu, nullptr, up, nullptr, I_DIM, H_DIM);
    gemm_mma_kernel<<<dim3(I_DIM/BN, M_ROWS/BM), 256, DSMEM>>>(
        xh, wgh, u, 64, 0,  Bg, up, nullptr, hbuf, I_DIM, H_DIM);

    lora_proj_kernel<__half><<<1024, 256>>>(hbuf, Ad, I_DIM, v, 32, 0);

    gemm_mma_kernel<<<dim3(H_DIM/BN, M_ROWS/BM), 256, DSMEM>>>(
        hbuf, wdh, v, 32, 0, Bd, nullptr, out, nullptr, H_DIM, I_DIM);
}